// round 10
// baseline (speedup 1.0000x reference)
#include <cuda_runtime.h>
#include <cuda_bf16.h>
#include <math.h>
#include <stdint.h>

#define BB 4096
#define DD 1024

#define THRESH   0.5f
#define MARGIN   0.1f
#define SCALE_P  2.0f
#define SCALE_N  40.0f
#define EPS      1e-5f

// Static scratch (no allocs).
__device__ float g_sim[(size_t)BB * BB];
__device__ __align__(16) __nv_bfloat16 g_xb[(size_t)BB * DD];
__device__ __align__(16) unsigned char g_lab8[BB];
__device__ float g_rowloss[BB];
__device__ int g_ctr = 0;

// ---------------------------------------------------------------------------
// Helpers
// ---------------------------------------------------------------------------
__device__ __forceinline__ uint32_t smem_u32(const void* p) {
    uint32_t a;
    asm("{ .reg .u64 t; cvta.to.shared.u64 t, %1; cvt.u32.u64 %0, t; }"
        : "=r"(a) : "l"(p));
    return a;
}
#define CP_ASYNC16(dst, src) \
    asm volatile("cp.async.cg.shared.global [%0], [%1], 16;" :: "r"(dst), "l"(src))
#define CP_COMMIT() asm volatile("cp.async.commit_group;" ::: "memory")
#define CP_WAIT(n)  asm volatile("cp.async.wait_group %0;" :: "n"(n) : "memory")

__device__ __forceinline__ void ldmatrix_x4(uint32_t& r0, uint32_t& r1,
                                            uint32_t& r2, uint32_t& r3,
                                            uint32_t addr) {
    asm volatile("ldmatrix.sync.aligned.m8n8.x4.shared.b16 {%0,%1,%2,%3}, [%4];"
                 : "=r"(r0), "=r"(r1), "=r"(r2), "=r"(r3) : "r"(addr));
}
__device__ __forceinline__ void mma_bf16(float& c0, float& c1, float& c2, float& c3,
                                         uint32_t a0, uint32_t a1, uint32_t a2,
                                         uint32_t a3, uint32_t b0, uint32_t b1) {
    asm volatile(
        "mma.sync.aligned.m16n8k16.row.col.f32.bf16.bf16.f32 "
        "{%0,%1,%2,%3}, {%4,%5,%6,%7}, {%8,%9}, {%0,%1,%2,%3};"
        : "+f"(c0), "+f"(c1), "+f"(c2), "+f"(c3)
        : "r"(a0), "r"(a1), "r"(a2), "r"(a3), "r"(b0), "r"(b1));
}

// ---------------------------------------------------------------------------
// Pass 0: f32 -> bf16 conversion of x + labels -> u8 (block 0).
// ---------------------------------------------------------------------------
__global__ __launch_bounds__(256) void convert_bf16(const float4* __restrict__ x,
                                                    const int* __restrict__ labels) {
#pragma unroll
    for (int q = 0; q < 2; q++) {
        const int i = blockIdx.x * 512 + q * 256 + threadIdx.x;
        float4 v = x[i];
        __nv_bfloat162 a = __floats2bfloat162_rn(v.x, v.y);
        __nv_bfloat162 b = __floats2bfloat162_rn(v.z, v.w);
        uint32_t pa, pb;
        memcpy(&pa, &a, 4); memcpy(&pb, &b, 4);
        ((uint2*)g_xb)[i] = make_uint2(pa, pb);
    }
    if (blockIdx.x == 0) {
        const int t = threadIdx.x;      // 16 labels each
#pragma unroll
        for (int k = 0; k < 4; k++) {
            int4 lv = *(const int4*)(labels + t * 16 + k * 4);
            uchar4 u;
            u.x = (unsigned char)lv.x; u.y = (unsigned char)lv.y;
            u.z = (unsigned char)lv.z; u.w = (unsigned char)lv.w;
            *(uchar4*)(g_lab8 + t * 16 + k * 4) = u;
        }
    }
}

// ---------------------------------------------------------------------------
// Pass 1: bf16 mma.sync symmetric GEMM.
// CTA tile 256x128, 8 warps (4x2), warp tile 64x64, K-chunk 64,
// 3-stage cp.async pipeline, triangular 272-CTA launch.
// ---------------------------------------------------------------------------
#define KC 64
#define ROWB 144                        // 64*2 + 16 pad
#define A_ROWS 256
#define B_ROWS 128
#define OFF_Bt (A_ROWS * ROWB)          // 36864
#define STAGE_B ((A_ROWS + B_ROWS) * ROWB)  // 55296
#define NSTAGE 3
#define SMEM_DYN (NSTAGE * STAGE_B)     // 165888
#define NRI 16                          // 256-row blocks
#define NCTA 272                        // sum_{RI} (32 - 2*RI)

__global__ __launch_bounds__(256, 1) void sim_gemm_mma() {
    // Triangular decode: tiles (RI, CJ) with CJ >= 2*RI.
    const int idx = blockIdx.x;
    int RI = 0, off = 0;
#pragma unroll 1
    while (off + (32 - 2 * RI) <= idx) { off += 32 - 2 * RI; RI++; }
    const int CJ = 2 * RI + (idx - off);

    extern __shared__ __align__(16) char smem[];
    const uint32_t sm = smem_u32(smem);

    const int tid = threadIdx.x;
    const int wid = tid >> 5, lane = tid & 31;
    const int warp_m = wid >> 1;          // 0..3  (64 rows each)
    const int warp_n = wid & 1;           // 0..1  (64 cols each)
    const int row0 = RI * 256, col0 = CJ * 128;

    float acc[4][8][4];
#pragma unroll
    for (int a = 0; a < 4; a++)
#pragma unroll
        for (int b = 0; b < 8; b++)
#pragma unroll
            for (int c = 0; c < 4; c++) acc[a][b][c] = 0.0f;

    const int a_mrow = warp_m * 64 + (lane & 7) + ((lane >> 3) & 1) * 8;
    const int a_kcol = (lane >> 4) << 3;
    const int b_nrow = warp_n * 64 + (lane & 7) + ((lane >> 4) << 3);
    const int b_kcol = ((lane >> 3) & 1) << 3;

    // Stage-load: 12 x 16B chunks per thread (A: 2048 chunks, B: 1024).
    // idx = p*256+tid ; r = idx>>3 (0..383) ; kc = idx&7 ; dst = r*ROWB+kc*16.
#define LOAD_STAGE(sbase, k0)                                                   \
    do {                                                                        \
        _Pragma("unroll")                                                       \
        for (int p = 0; p < 12; p++) {                                          \
            const int ii = p * 256 + tid;                                       \
            const int r = ii >> 3, kc = ii & 7;                                 \
            const uint32_t d = (sbase) + (uint32_t)(r * ROWB + kc * 16);        \
            const uint32_t go = (uint32_t)(((p < 8) ? (row0 + r)                \
                                                    : (col0 + r - 256)) * DD    \
                                           + kc * 8 + (k0));                    \
            CP_ASYNC16(d, g_xb + go);                                           \
        }                                                                       \
        CP_COMMIT();                                                            \
    } while (0)

    // Prologue: stages 0 and 1.
    LOAD_STAGE(sm, 0);
    LOAD_STAGE(sm + STAGE_B, KC);

    for (int ck = 0; ck < DD / KC; ck++) {
        if (ck < DD / KC - 1) { CP_WAIT(1); } else { CP_WAIT(0); }
        __syncthreads();   // stage ck ready; compute(ck-1) finished everywhere

        if (ck + 2 < DD / KC) {
            LOAD_STAGE(sm + ((ck + 2) % NSTAGE) * STAGE_B, (ck + 2) * KC);
        }

        const uint32_t stA = sm + (ck % NSTAGE) * STAGE_B;
        const uint32_t stB = stA + OFF_Bt;

#pragma unroll
        for (int ks = 0; ks < KC / 16; ks++) {
            uint32_t af[4][4], bf[4][4];
#pragma unroll
            for (int mf = 0; mf < 4; mf++)
                ldmatrix_x4(af[mf][0], af[mf][1], af[mf][2], af[mf][3],
                            stA + (uint32_t)((a_mrow + mf * 16) * ROWB
                                             + (ks * 16 + a_kcol) * 2));
#pragma unroll
            for (int nfp = 0; nfp < 4; nfp++)
                ldmatrix_x4(bf[nfp][0], bf[nfp][1], bf[nfp][2], bf[nfp][3],
                            stB + (uint32_t)((b_nrow + nfp * 16) * ROWB
                                             + (ks * 16 + b_kcol) * 2));
#pragma unroll
            for (int mf = 0; mf < 4; mf++)
#pragma unroll
                for (int nf = 0; nf < 8; nf++) {
                    const uint32_t b0 = bf[nf >> 1][(nf & 1) * 2];
                    const uint32_t b1 = bf[nf >> 1][(nf & 1) * 2 + 1];
                    mma_bf16(acc[mf][nf][0], acc[mf][nf][1],
                             acc[mf][nf][2], acc[mf][nf][3],
                             af[mf][0], af[mf][1], af[mf][2], af[mf][3], b0, b1);
                }
        }
    }
    __syncthreads();   // all smem reads done before epilogue reuse

    // Epilogue in two 128x128 halves through stride-129 smem.
    float* smf = (float*)smem;
    const int my_half = warp_m >> 1;
    const int r_lo = (warp_m & 1) * 64 + (lane >> 2);
    const int c_lo = warp_n * 64 + (lane & 3) * 2;
    const int cc = tid & 127;
    const int rh = tid >> 7;

#pragma unroll
    for (int h = 0; h < 2; h++) {
        if (my_half == h) {
#pragma unroll
            for (int mf = 0; mf < 4; mf++)
#pragma unroll
                for (int nf = 0; nf < 8; nf++) {
                    const int r = r_lo + mf * 16;
                    const int c = c_lo + nf * 8;
                    smf[r * 129 + c]           = acc[mf][nf][0];
                    smf[r * 129 + c + 1]       = acc[mf][nf][1];
                    smf[(r + 8) * 129 + c]     = acc[mf][nf][2];
                    smf[(r + 8) * 129 + c + 1] = acc[mf][nf][3];
                }
        }
        __syncthreads();

        const int gr0 = row0 + h * 128;
        // Direct 128x128 (coalesced stores, conflict-free LDS).
#pragma unroll 4
        for (int i = 0; i < 64; i++) {
            const int r = i * 2 + rh;
            g_sim[(size_t)(gr0 + r) * BB + col0 + cc] = smf[r * 129 + cc];
        }
        // Mirror 128x128 (duplicate writes on straddling tiles are bitwise
        // identical: dot(x_a,x_b) == dot(x_b,x_a) under identical k-order).
#pragma unroll 4
        for (int i = 0; i < 64; i++) {
            const int r = i * 2 + rh;
            g_sim[(size_t)(col0 + r) * BB + gr0 + cc] = smf[cc * 129 + r];
        }
        __syncthreads();
    }
}

// ---------------------------------------------------------------------------
// Pass 2: per-row mining + mined sums + fused final reduction (last block).
// ---------------------------------------------------------------------------
__global__ __launch_bounds__(256) void row_pass(float* __restrict__ out) {
    const int i = blockIdx.x;
    const int tid = threadIdx.x;
    const int wid = tid >> 5, lane = tid & 31;

    __shared__ float srow[BB];
    __shared__ unsigned char slab[BB];
    __shared__ float wr0[8], wr1[8];
    __shared__ int   wri[8];
    __shared__ float s_mp, s_mn;
    __shared__ int   s_last;

    *(uint4*)(slab + tid * 16) = ((const uint4*)g_lab8)[tid];
    const float* simrow = &g_sim[(size_t)i * BB];
#pragma unroll
    for (int c = 0; c < 4; c++) {
        const int j = c * 1024 + tid * 4;
        *(float4*)(srow + j) = *(const float4*)(simrow + j);
    }
    __syncthreads();

    const unsigned char li = slab[i];

    float minp = INFINITY, maxn = -INFINITY;
#pragma unroll
    for (int c = 0; c < 4; c++) {
        const int j0 = c * 1024 + tid * 4;
        const float4 v = *(const float4*)(srow + j0);
        const uint32_t lw = *(const uint32_t*)(slab + j0);
        const float sv[4] = {v.x, v.y, v.z, v.w};
#pragma unroll
        for (int e = 0; e < 4; e++) {
            const int j = j0 + e;
            const float s = sv[e];
            if (((lw >> (e * 8)) & 255u) == li) {
                if (j != i && s < 1.0f - EPS) minp = fminf(minp, s);
            } else {
                maxn = fmaxf(maxn, s);
            }
        }
    }
#pragma unroll
    for (int o = 16; o > 0; o >>= 1) {
        minp = fminf(minp, __shfl_xor_sync(0xFFFFFFFFu, minp, o));
        maxn = fmaxf(maxn, __shfl_xor_sync(0xFFFFFFFFu, maxn, o));
    }
    if (lane == 0) { wr0[wid] = minp; wr1[wid] = maxn; }
    __syncthreads();
    if (tid == 0) {
        float mp = wr0[0], mn = wr1[0];
#pragma unroll
        for (int w = 1; w < 8; w++) { mp = fminf(mp, wr0[w]); mn = fmaxf(mn, wr1[w]); }
        s_mp = mp; s_mn = mn;
    }
    __syncthreads();
    const float mp = s_mp, mn = s_mn;

    float psum = 0.0f, nsum = 0.0f;
    int flags = 0;
#pragma unroll
    for (int c = 0; c < 4; c++) {
        const int j0 = c * 1024 + tid * 4;
        const float4 v = *(const float4*)(srow + j0);
        const uint32_t lw = *(const uint32_t*)(slab + j0);
        const float sv[4] = {v.x, v.y, v.z, v.w};
#pragma unroll
        for (int e = 0; e < 4; e++) {
            const int j = j0 + e;
            const float s = sv[e];
            if (((lw >> (e * 8)) & 255u) != li) {
                if (s + MARGIN > mp) { nsum += __expf(SCALE_N * (s - THRESH)); flags |= 2; }
            } else if (j != i && s < 1.0f - EPS) {
                if (s - MARGIN < mn) { psum += __expf(-SCALE_P * (s - THRESH)); flags |= 1; }
            }
        }
    }
#pragma unroll
    for (int o = 16; o > 0; o >>= 1) {
        psum += __shfl_xor_sync(0xFFFFFFFFu, psum, o);
        nsum += __shfl_xor_sync(0xFFFFFFFFu, nsum, o);
        flags |= __shfl_xor_sync(0xFFFFFFFFu, flags, o);
    }
    if (lane == 0) { wr0[wid] = psum; wr1[wid] = nsum; wri[wid] = flags; }
    __syncthreads();

    if (tid == 0) {
        float ps = wr0[0], ns = wr1[0];
        int fl = wri[0];
#pragma unroll
        for (int w = 1; w < 8; w++) { ps += wr0[w]; ns += wr1[w]; fl |= wri[w]; }
        const bool has_row = isfinite(mp) && (mn > -INFINITY) && (fl & 1) && (fl & 2);
        float loss = 0.0f;
        if (has_row) loss = log1pf(ps) / SCALE_P + log1pf(ns) / SCALE_N;
        g_rowloss[i] = loss;
        __threadfence();
        const int old = atomicAdd(&g_ctr, 1);
        s_last = (old == BB - 1) ? 1 : 0;
    }
    __syncthreads();

    if (s_last) {
        __threadfence();
        float s = 0.0f;
        for (int k = tid; k < BB; k += 256) s += __ldcg(&g_rowloss[k]);
#pragma unroll
        for (int o = 16; o > 0; o >>= 1) s += __shfl_xor_sync(0xFFFFFFFFu, s, o);
        if (lane == 0) wr0[wid] = s;
        __syncthreads();
        if (tid == 0) {
            float t = 0.0f;
#pragma unroll
            for (int w = 0; w < 8; w++) t += wr0[w];
            out[0] = t / (float)BB;
            g_ctr = 0;   // reset for next graph replay
        }
    }
}

extern "C" void kernel_launch(void* const* d_in, const int* in_sizes, int n_in,
                              void* d_out, int out_size) {
    const float* x = (const float*)d_in[0];
    const int* labels = (const int*)d_in[1];
    float* out = (float*)d_out;

    cudaFuncSetAttribute(sim_gemm_mma, cudaFuncAttributeMaxDynamicSharedMemorySize,
                         SMEM_DYN);

    convert_bf16<<<(BB * DD / 4) / 512, 256>>>((const float4*)x, labels);
    sim_gemm_mma<<<NCTA, 256, SMEM_DYN>>>();
    row_pass<<<BB, 256>>>(out);
}